// round 1
// baseline (speedup 1.0000x reference)
#include <cuda_runtime.h>

// ---------------------------------------------------------------------------
// SimpleMACELayerFused, restructured:
//   out[t,:] = b + sum_{e: tgt=t} ( Y_e[0:16] . G[src_e, 0:16, :] )
//   G[s,i,c] = sum_h f[s,h] * W[h*16+i, c]
// G stored as G[s][c][i]  (lane c of a warp reads its 16 contiguous floats).
// ---------------------------------------------------------------------------

#define MAX_ATOMS 50000
__device__ float g_G[(size_t)MAX_ATOMS * 512];   // 102.4 MB scratch
__device__ int   g_is64;

// --- Kernel 0: detect whether edge_index is int64 or int32 -----------------
// For int64 (values in [0, 50000)), every odd 32-bit word is a zero high-half.
// For int32, odd words are random indices -> OR over 4096 of them is nonzero.
__global__ void detect_kernel(const unsigned int* __restrict__ idx_words,
                              int nwords_check) {
    __shared__ unsigned int red[256];
    unsigned int acc = 0;
    for (int w = 1 + 2 * (int)threadIdx.x; w < nwords_check; w += 2 * (int)blockDim.x)
        acc |= idx_words[w];
    red[threadIdx.x] = acc;
    __syncthreads();
    for (int s = 128; s > 0; s >>= 1) {
        if ((int)threadIdx.x < s) red[threadIdx.x] |= red[threadIdx.x + s];
        __syncthreads();
    }
    if (threadIdx.x == 0) g_is64 = (red[0] == 0u) ? 1 : 0;
}

// --- Kernel 1: G[s][c*16+i] = sum_h f[s,h] * W[(h*16+i)*32 + c] ------------
// 512 threads: thread j owns output column j = c*16+i, holds its 32 W values
// in registers. Node tiles of 32 staged through smem (broadcast reads).
__global__ void g_build_kernel(const float* __restrict__ f,
                               const float* __restrict__ W,
                               int n_atoms) {
    __shared__ float fs[32][32];
    const int j = threadIdx.x;          // 0..511
    const int c = j >> 4;
    const int i = j & 15;

    float w[32];
#pragma unroll
    for (int h = 0; h < 32; h++)
        w[h] = W[(h * 16 + i) * 32 + c];

    const int ntiles = (n_atoms + 31) >> 5;
    for (int tile = blockIdx.x; tile < ntiles; tile += gridDim.x) {
        const int n0 = tile << 5;
        const int nrows = min(32, n_atoms - n0);
        __syncthreads();  // previous tile's reads done
        for (int t = j; t < nrows * 32; t += 512)
            fs[t >> 5][t & 31] = f[(size_t)n0 * 32 + t];
        __syncthreads();
        for (int n = 0; n < nrows; n++) {
            float acc = 0.f;
#pragma unroll
            for (int h = 0; h < 32; h++)
                acc = fmaf(fs[n][h], w[h], acc);
            g_G[(size_t)(n0 + n) * 512 + j] = acc;
        }
    }
}

// --- Kernel 2: out[t*32+c] = b[c]  (also unpoisons the output) -------------
__global__ void init_out_kernel(float* __restrict__ out,
                                const float* __restrict__ b, int total) {
    int g = blockIdx.x * blockDim.x + threadIdx.x;
    if (g < total) out[g] = b[g & 31];
}

// --- Kernel 3: per-edge accumulate: warp per edge --------------------------
__global__ void edge_kernel(const float* __restrict__ ev,
                            const int* __restrict__ idx_words,
                            float* __restrict__ out,
                            int n_edges) {
    const int lane   = threadIdx.x & 31;
    const int warp   = (int)((blockIdx.x * blockDim.x + threadIdx.x) >> 5);
    const int nwarps = (int)((gridDim.x * blockDim.x) >> 5);

    const int is64   = g_is64;
    const int stride = is64 ? 2 : 1;
    const int* __restrict__ sbase = idx_words;
    const int* __restrict__ tbase = idx_words + ((size_t)n_edges * (is64 ? 2 : 1));

    for (int e = warp; e < n_edges; e += nwarps) {
        const int src = sbase[(size_t)e * stride];
        const int tgt = tbase[(size_t)e * stride];

        const float vx = ev[(size_t)e * 3 + 0];
        const float vy = ev[(size_t)e * 3 + 1];
        const float vz = ev[(size_t)e * 3 + 2];
        const float r2 = vx * vx + vy * vy + vz * vz;
        const float r  = sqrtf(r2);
        const float inv = 1.0f / fmaxf(r, 1e-12f);
        const float x = vx * inv, y = vy * inv, z = vz * inv;
        const float x2 = x * x, y2 = y * y, z2 = z * z;

        const float Y0  = 0.28209479177387814f;
        const float Y1  = 0.4886025119029199f * y;
        const float Y2  = 0.4886025119029199f * z;
        const float Y3  = 0.4886025119029199f * x;
        const float Y4  = 1.0925484305920792f * x * y;
        const float Y5  = 1.0925484305920792f * y * z;
        const float Y6  = 0.31539156525252005f * (3.0f * z2 - 1.0f);
        const float Y7  = 1.0925484305920792f * x * z;
        const float Y8  = 0.5462742152960396f * (x2 - y2);
        const float Y9  = 0.5900435899266435f * y * (3.0f * x2 - y2);
        const float Y10 = 2.890611442640554f * x * y * z;
        const float Y11 = 0.4570457994644658f * y * (5.0f * z2 - 1.0f);
        const float Y12 = 0.3731763325901154f * z * (5.0f * z2 - 3.0f);
        const float Y13 = 0.4570457994644658f * x * (5.0f * z2 - 1.0f);
        const float Y14 = 1.445305721320277f * z * (x2 - y2);
        const float Y15 = 0.5900435899266435f * x * (x2 - 3.0f * y2);

        const float4* __restrict__ g =
            reinterpret_cast<const float4*>(g_G + (size_t)src * 512 + lane * 16);
        const float4 g0 = g[0], g1 = g[1], g2 = g[2], g3 = g[3];

        float m = Y0 * g0.x;
        m = fmaf(Y1,  g0.y, m); m = fmaf(Y2,  g0.z, m); m = fmaf(Y3,  g0.w, m);
        m = fmaf(Y4,  g1.x, m); m = fmaf(Y5,  g1.y, m);
        m = fmaf(Y6,  g1.z, m); m = fmaf(Y7,  g1.w, m);
        m = fmaf(Y8,  g2.x, m); m = fmaf(Y9,  g2.y, m);
        m = fmaf(Y10, g2.z, m); m = fmaf(Y11, g2.w, m);
        m = fmaf(Y12, g3.x, m); m = fmaf(Y13, g3.y, m);
        m = fmaf(Y14, g3.z, m); m = fmaf(Y15, g3.w, m);

        atomicAdd(out + (size_t)tgt * 32 + lane, m);   // REDG, coalesced per warp
    }
}

extern "C" void kernel_launch(void* const* d_in, const int* in_sizes, int n_in,
                              void* d_out, int out_size) {
    const float* f   = (const float*)d_in[0];   // node_features [n_atoms,32]
    const float* ev  = (const float*)d_in[1];   // edge_vectors  [n_edges,3]
    const int*   idx = (const int*)d_in[2];     // edge_index [2,n_edges] (32 or 64 bit)
    const float* W   = (const float*)d_in[3];   // [512,32]
    const float* b   = (const float*)d_in[4];   // [32]
    float* out = (float*)d_out;

    const int n_atoms = in_sizes[0] / 32;
    const int n_edges = in_sizes[1] / 3;
    const int total   = out_size;               // n_atoms * 32

    int ncheck = 2 * n_edges;
    if (ncheck > 8192) ncheck = 8192;
    detect_kernel<<<1, 256>>>((const unsigned int*)idx, ncheck);

    g_build_kernel<<<444, 512>>>(f, W, n_atoms);

    init_out_kernel<<<(total + 255) / 256, 256>>>(out, b, total);

    edge_kernel<<<592, 256>>>(ev, idx, out, n_edges);
}

// round 2
// speedup vs baseline: 1.0577x; 1.0577x over previous
#include <cuda_runtime.h>

// ---------------------------------------------------------------------------
// out[t,:] = b + ( Σ_{e->t} f[src_e] ⊗ Y_e ).reshape(512) @ W
// Phase 1: counting-sort edges by target (hist -> scan -> scatter)
// Phase 2: accum: warp per target, M[t,h,i] in registers (no atomics)
// Phase 3: tiled GEMM M[50000,512] @ W[512,32] + b
// ---------------------------------------------------------------------------

#define MAX_ATOMS 50016
#define MAX_EDGES 800000

__device__ float g_M[(size_t)MAX_ATOMS * 512];   // ~102 MB scratch
__device__ int   g_cnt[MAX_ATOMS + 1];
__device__ int   g_start[MAX_ATOMS + 1];
__device__ int   g_cur[MAX_ATOMS + 1];
__device__ int   g_order[MAX_EDGES];
__device__ int   g_is64;

// --- prep: zero counts; block 0 also detects int64-vs-int32 edge_index -----
__global__ void prep_kernel(const unsigned int* __restrict__ idx_words,
                            int nwords_check, int n_atoms) {
    int gid = blockIdx.x * blockDim.x + threadIdx.x;
    for (int i = gid; i <= n_atoms; i += gridDim.x * blockDim.x) g_cnt[i] = 0;

    if (blockIdx.x == 0) {
        __shared__ unsigned int red[256];
        unsigned int acc = 0;
        for (int w = 1 + 2 * (int)threadIdx.x; w < nwords_check; w += 2 * (int)blockDim.x)
            acc |= idx_words[w];
        red[threadIdx.x] = acc;
        __syncthreads();
        for (int s = 128; s > 0; s >>= 1) {
            if ((int)threadIdx.x < s) red[threadIdx.x] |= red[threadIdx.x + s];
            __syncthreads();
        }
        if (threadIdx.x == 0) g_is64 = (red[0] == 0u) ? 1 : 0;
    }
}

// --- histogram of targets --------------------------------------------------
__global__ void hist_kernel(const int* __restrict__ idx, int n_edges) {
    const int stride = g_is64 ? 2 : 1;
    const int* __restrict__ tb = idx + (size_t)n_edges * stride;
    int gid = blockIdx.x * blockDim.x + threadIdx.x;
    for (int e = gid; e < n_edges; e += gridDim.x * blockDim.x)
        atomicAdd(&g_cnt[tb[(size_t)e * stride]], 1);
}

// --- exclusive scan over g_cnt[0..n_atoms) -> g_start, g_cur ---------------
__global__ void scan_kernel(int n_atoms) {
    __shared__ int s1[1024];
    const int tid = threadIdx.x;
    const int chunk = (n_atoms + 1023) / 1024;
    const int lo = tid * chunk;
    const int hi = min(lo + chunk, n_atoms);

    int local = 0;
    for (int i = lo; i < hi; i++) local += g_cnt[i];
    s1[tid] = local;
    __syncthreads();
    for (int d = 1; d < 1024; d <<= 1) {
        int v = (tid >= d) ? s1[tid - d] : 0;
        __syncthreads();
        s1[tid] += v;
        __syncthreads();
    }
    int off = s1[tid] - local;   // exclusive prefix
    for (int i = lo; i < hi; i++) {
        g_start[i] = off;
        g_cur[i]   = off;
        off += g_cnt[i];
    }
    if (tid == 1023) g_start[n_atoms] = s1[1023];
}

// --- scatter edge ids into target-sorted order -----------------------------
__global__ void scatter_kernel(const int* __restrict__ idx, int n_edges) {
    const int stride = g_is64 ? 2 : 1;
    const int* __restrict__ tb = idx + (size_t)n_edges * stride;
    int gid = blockIdx.x * blockDim.x + threadIdx.x;
    for (int e = gid; e < n_edges; e += gridDim.x * blockDim.x) {
        int tgt = tb[(size_t)e * stride];
        int pos = atomicAdd(&g_cur[tgt], 1);
        g_order[pos] = e;
    }
}

// --- accum: warp per target; lane = h; M[t,h,0..15] in registers -----------
__global__ void accum_kernel(const float* __restrict__ ev,
                             const int* __restrict__ idx,
                             const float* __restrict__ f,
                             int n_edges, int n_atoms) {
    const int lane = threadIdx.x & 31;
    const int t = (int)((blockIdx.x * blockDim.x + threadIdx.x) >> 5);
    if (t >= n_atoms) return;

    const int stride = g_is64 ? 2 : 1;
    const int* __restrict__ sb = idx;

    const int start = g_start[t];
    const int end   = g_start[t + 1];

    float m[16];
#pragma unroll
    for (int i = 0; i < 16; i++) m[i] = 0.f;

    for (int p = start; p < end; p++) {
        const int e   = g_order[p];
        const int src = sb[(size_t)e * stride];

        const float vx = ev[(size_t)e * 3 + 0];
        const float vy = ev[(size_t)e * 3 + 1];
        const float vz = ev[(size_t)e * 3 + 2];
        const float fh = f[(size_t)src * 32 + lane];

        const float r2 = vx * vx + vy * vy + vz * vz;
        const float r  = sqrtf(r2);
        const float inv = 1.0f / fmaxf(r, 1e-12f);
        const float x = vx * inv, y = vy * inv, z = vz * inv;
        const float x2 = x * x, y2 = y * y, z2 = z * z;

        const float Y0  = 0.28209479177387814f;
        const float Y1  = 0.4886025119029199f * y;
        const float Y2  = 0.4886025119029199f * z;
        const float Y3  = 0.4886025119029199f * x;
        const float Y4  = 1.0925484305920792f * x * y;
        const float Y5  = 1.0925484305920792f * y * z;
        const float Y6  = 0.31539156525252005f * (3.0f * z2 - 1.0f);
        const float Y7  = 1.0925484305920792f * x * z;
        const float Y8  = 0.5462742152960396f * (x2 - y2);
        const float Y9  = 0.5900435899266435f * y * (3.0f * x2 - y2);
        const float Y10 = 2.890611442640554f * x * y * z;
        const float Y11 = 0.4570457994644658f * y * (5.0f * z2 - 1.0f);
        const float Y12 = 0.3731763325901154f * z * (5.0f * z2 - 3.0f);
        const float Y13 = 0.4570457994644658f * x * (5.0f * z2 - 1.0f);
        const float Y14 = 1.445305721320277f * z * (x2 - y2);
        const float Y15 = 0.5900435899266435f * x * (x2 - 3.0f * y2);

        m[0]  = fmaf(fh, Y0,  m[0]);  m[1]  = fmaf(fh, Y1,  m[1]);
        m[2]  = fmaf(fh, Y2,  m[2]);  m[3]  = fmaf(fh, Y3,  m[3]);
        m[4]  = fmaf(fh, Y4,  m[4]);  m[5]  = fmaf(fh, Y5,  m[5]);
        m[6]  = fmaf(fh, Y6,  m[6]);  m[7]  = fmaf(fh, Y7,  m[7]);
        m[8]  = fmaf(fh, Y8,  m[8]);  m[9]  = fmaf(fh, Y9,  m[9]);
        m[10] = fmaf(fh, Y10, m[10]); m[11] = fmaf(fh, Y11, m[11]);
        m[12] = fmaf(fh, Y12, m[12]); m[13] = fmaf(fh, Y13, m[13]);
        m[14] = fmaf(fh, Y14, m[14]); m[15] = fmaf(fh, Y15, m[15]);
    }

    // M[t][h*16 + i], lane h writes its 16 contiguous floats
    float4* dst = reinterpret_cast<float4*>(g_M + (size_t)t * 512 + lane * 16);
    dst[0] = make_float4(m[0],  m[1],  m[2],  m[3]);
    dst[1] = make_float4(m[4],  m[5],  m[6],  m[7]);
    dst[2] = make_float4(m[8],  m[9],  m[10], m[11]);
    dst[3] = make_float4(m[12], m[13], m[14], m[15]);
}

// --- GEMM: out[t,c] = b[c] + sum_k M[t,k]*W[k,c] ---------------------------
// Block: 128 threads, tile = 64 targets x 32 c, 4x4 register blocking.
#define GT 64
__global__ void gemm_kernel(const float* __restrict__ W,
                            const float* __restrict__ b,
                            float* __restrict__ out, int n_atoms) {
    __shared__ float Ms[GT][33];
    __shared__ float Ws[32][32];

    const int tid = threadIdx.x;       // 0..127
    const int tx  = tid & 7;           // c group (4 c each)
    const int ty  = tid >> 3;          // t group (4 t each), 0..15
    const int t0  = blockIdx.x * GT;

    float acc[4][4];
#pragma unroll
    for (int j = 0; j < 4; j++)
#pragma unroll
        for (int i = 0; i < 4; i++) acc[j][i] = 0.f;

    for (int k0 = 0; k0 < 512; k0 += 32) {
        __syncthreads();
        // load M tile [64][32]: 512 float4, 4 per thread
        for (int v = tid; v < GT * 8; v += 128) {
            const int row  = v >> 3;
            const int col4 = v & 7;
            float4 val = make_float4(0.f, 0.f, 0.f, 0.f);
            const int t = t0 + row;
            if (t < n_atoms)
                val = *reinterpret_cast<const float4*>(
                    g_M + (size_t)t * 512 + k0 + col4 * 4);
            Ms[row][col4 * 4 + 0] = val.x;
            Ms[row][col4 * 4 + 1] = val.y;
            Ms[row][col4 * 4 + 2] = val.z;
            Ms[row][col4 * 4 + 3] = val.w;
        }
        // load W chunk [32][32]: 256 float4, 2 per thread
        for (int v = tid; v < 32 * 8; v += 128) {
            const int row  = v >> 3;
            const int col4 = v & 7;
            float4 val = *reinterpret_cast<const float4*>(
                W + (size_t)(k0 + row) * 32 + col4 * 4);
            *reinterpret_cast<float4*>(&Ws[row][col4 * 4]) = val;
        }
        __syncthreads();

#pragma unroll
        for (int kk = 0; kk < 32; kk++) {
            const float4 wv = *reinterpret_cast<const float4*>(&Ws[kk][tx * 4]);
            float a[4];
#pragma unroll
            for (int j = 0; j < 4; j++) a[j] = Ms[ty * 4 + j][kk];
#pragma unroll
            for (int j = 0; j < 4; j++) {
                acc[j][0] = fmaf(a[j], wv.x, acc[j][0]);
                acc[j][1] = fmaf(a[j], wv.y, acc[j][1]);
                acc[j][2] = fmaf(a[j], wv.z, acc[j][2]);
                acc[j][3] = fmaf(a[j], wv.w, acc[j][3]);
            }
        }
    }

    const float4 bv = *reinterpret_cast<const float4*>(b + tx * 4);
#pragma unroll
    for (int j = 0; j < 4; j++) {
        const int t = t0 + ty * 4 + j;
        if (t < n_atoms) {
            float4 o = make_float4(acc[j][0] + bv.x, acc[j][1] + bv.y,
                                   acc[j][2] + bv.z, acc[j][3] + bv.w);
            *reinterpret_cast<float4*>(out + (size_t)t * 32 + tx * 4) = o;
        }
    }
}

extern "C" void kernel_launch(void* const* d_in, const int* in_sizes, int n_in,
                              void* d_out, int out_size) {
    const float* f   = (const float*)d_in[0];   // [n_atoms,32]
    const float* ev  = (const float*)d_in[1];   // [n_edges,3]
    const int*   idx = (const int*)d_in[2];     // [2,n_edges] int32 or int64
    const float* W   = (const float*)d_in[3];   // [512,32]
    const float* b   = (const float*)d_in[4];   // [32]
    float* out = (float*)d_out;

    const int n_atoms = in_sizes[0] / 32;
    const int n_edges = in_sizes[1] / 3;

    int ncheck = 2 * n_edges;
    if (ncheck > 8192) ncheck = 8192;

    prep_kernel<<<64, 256>>>((const unsigned int*)idx, ncheck, n_atoms);
    hist_kernel<<<592, 256>>>(idx, n_edges);
    scan_kernel<<<1, 1024>>>(n_atoms);
    scatter_kernel<<<592, 256>>>(idx, n_edges);

    const int ablocks = (n_atoms * 32 + 255) / 256;
    accum_kernel<<<ablocks, 256>>>(ev, idx, f, n_edges, n_atoms);

    const int gblocks = (n_atoms + GT - 1) / GT;
    gemm_kernel<<<gblocks, 128>>>(W, b, out, n_atoms);
}